// round 14
// baseline (speedup 1.0000x reference)
#include <cuda_runtime.h>
#include <math.h>

#define B   2
#define L   2048
#define HS  2048
#define NH  16
#define NKV 4
#define HD  128
#define BL  (B*L)
#define EPS 1e-6f
#define SCALE 0.08838834764831845f   // 128^-0.5

// ---------------- scratch (static device memory: alloc-guard safe) ----------
__device__ float g_q[(size_t)BL*NH*HD];     // 33.5 MB
__device__ float g_k[(size_t)BL*NKV*HD];    // 8.4 MB
__device__ float g_v[(size_t)BL*NKV*HD];    // 8.4 MB
__device__ float g_att[(size_t)BL*NH*HD];   // 33.5 MB
__device__ float g_cos[L*(HD/2)];
__device__ float g_sin[L*(HD/2)];

// ---------------- RoPE table (fp64 for accuracy, tiny kernel) ---------------
__global__ void rope_table_kernel() {
    int idx = blockIdx.x * blockDim.x + threadIdx.x;
    if (idx >= L*(HD/2)) return;
    int l = idx / (HD/2);
    int i = idx % (HD/2);
    // inv_freq = 10000^(-i/64) = exp(-i * ln(10000)/64)
    double inv = exp(-(double)i * (9.210340371976184 / 64.0));
    double a = (double)l * inv;
    g_cos[idx] = (float)cos(a);
    g_sin[idx] = (float)sin(a);
}

// ---------------- tiled fp32 SGEMM: C[M,N] = A[M,K] @ Bm[K,N] ----------------
#define BM 64
#define BN 64
#define BK 16
__global__ __launch_bounds__(256)
void sgemm_kernel(const float* __restrict__ A, const float* __restrict__ Bm,
                  float* __restrict__ C, int M, int N, int K) {
    __shared__ float As[BK][BM+1];
    __shared__ float Bs[BK][BN];
    int tid = threadIdx.x;
    int tx = tid & 15, ty = tid >> 4;
    int bm = blockIdx.y * BM, bn = blockIdx.x * BN;
    int arow = tid >> 2,  acol = (tid & 3) << 2;     // A: 64 rows x 16 cols, float4/thread
    int brow = tid >> 4,  bcol = (tid & 15) << 2;    // B: 16 rows x 64 cols, float4/thread
    const float* Aptr = A + (size_t)(bm + arow) * K + acol;
    const float* Bptr = Bm + (size_t)brow * N + bn + bcol;
    float acc[4][4] = {};
    for (int k0 = 0; k0 < K; k0 += BK) {
        float4 av = *(const float4*)(Aptr + k0);
        As[acol+0][arow] = av.x; As[acol+1][arow] = av.y;
        As[acol+2][arow] = av.z; As[acol+3][arow] = av.w;
        float4 bv = *(const float4*)(Bptr + (size_t)k0 * N);
        *(float4*)&Bs[brow][bcol] = bv;
        __syncthreads();
        #pragma unroll
        for (int k = 0; k < BK; k++) {
            float ra[4], rb[4];
            #pragma unroll
            for (int i = 0; i < 4; i++) ra[i] = As[k][(ty<<2)+i];
            #pragma unroll
            for (int j = 0; j < 4; j++) rb[j] = Bs[k][(tx<<2)+j];
            #pragma unroll
            for (int i = 0; i < 4; i++)
                #pragma unroll
                for (int j = 0; j < 4; j++)
                    acc[i][j] = fmaf(ra[i], rb[j], acc[i][j]);
        }
        __syncthreads();
    }
    #pragma unroll
    for (int i = 0; i < 4; i++) {
        float4 v = make_float4(acc[i][0], acc[i][1], acc[i][2], acc[i][3]);
        *(float4*)&C[(size_t)(bm + (ty<<2) + i) * N + bn + (tx<<2)] = v;
    }
}

// ---------------- fused RMSNorm (over HD) + RoPE, in-place -------------------
__global__ __launch_bounds__(HD)
void norm_rope_kernel(float* __restrict__ x, const float* __restrict__ w, int nheads) {
    int idx = blockIdx.x;              // (b*L + l)*nheads + h
    int tok = idx / nheads;
    int l   = tok % L;
    int d   = threadIdx.x;             // 0..127
    float* xp = x + (size_t)idx * HD;
    float v = xp[d];
    float ss = v * v;
    #pragma unroll
    for (int o = 16; o; o >>= 1) ss += __shfl_xor_sync(0xffffffffu, ss, o);
    __shared__ float wsum[4];
    if ((d & 31) == 0) wsum[d >> 5] = ss;
    __syncthreads();
    float total = wsum[0] + wsum[1] + wsum[2] + wsum[3];
    float r = rsqrtf(total * (1.0f/HD) + EPS);
    float xn = v * r * w[d];
    __shared__ float sx[HD];
    sx[d] = xn;
    __syncthreads();
    int fi = d & 63;
    float cz = g_cos[l*(HD/2) + fi];
    float sz = g_sin[l*(HD/2) + fi];
    float out;
    if (d < 64) out = xn * cz - sx[d+64] * sz;   // x1*cos - x2*sin
    else        out = xn * cz + sx[d-64] * sz;   // x2*cos + x1*sin
    xp[d] = out;
}

// ---------------- flash-style causal GQA attention ---------------------------
// 32 queries/block, 4 threads per query, each thread owns dims {c, c+4, ..., c+124}.
// Interleaved dim mapping -> smem reads hit 4 distinct banks (conflict-free).
#define QB 32
#define KT 32
__global__ __launch_bounds__(128)
void attn_kernel() {
    int b = blockIdx.z, h = blockIdx.y, qt = blockIdx.x;
    int j = h & (NKV - 1);             // GQA: q head h -> kv head h % NKV
    int tid = threadIdx.x;
    int ql = tid >> 2, c = tid & 3;
    int qpos = qt * QB + ql;

    const float* qptr = g_q + ((size_t)(b*L + qpos) * NH + h) * HD;
    float qr[32];
    #pragma unroll
    for (int i = 0; i < 32; i++) qr[i] = qptr[c + 4*i] * SCALE;

    float o[32];
    #pragma unroll
    for (int i = 0; i < 32; i++) o[i] = 0.f;
    float m = -INFINITY, lsum = 0.f;

    __shared__ float Ks[KT][HD];
    __shared__ float Vs[KT][HD];

    for (int kt = 0; kt <= qt; kt++) {
        // cooperative load: 32x128 floats each for K and V, 8 float4 per thread
        #pragma unroll
        for (int t = 0; t < 8; t++) {
            int fi  = tid + t * 128;
            int row = fi >> 5;
            int col = (fi & 31) << 2;
            size_t goff = ((size_t)(b*L + kt*KT + row) * NKV + j) * HD + col;
            *(float4*)&Ks[row][col] = *(const float4*)(g_k + goff);
            *(float4*)&Vs[row][col] = *(const float4*)(g_v + goff);
        }
        __syncthreads();

        #pragma unroll 4
        for (int kk = 0; kk < KT; kk++) {
            float s = 0.f;
            #pragma unroll
            for (int i = 0; i < 32; i++)
                s = fmaf(qr[i], Ks[kk][c + 4*i], s);
            s += __shfl_xor_sync(0xffffffffu, s, 1);
            s += __shfl_xor_sync(0xffffffffu, s, 2);
            if (kt*KT + kk <= qpos) {
                if (s > m) {                      // rescale only on new max
                    float corr = __expf(m - s);   // m=-inf first time -> corr=0
                    lsum *= corr;
                    #pragma unroll
                    for (int i = 0; i < 32; i++) o[i] *= corr;
                    m = s;
                }
                float p = __expf(s - m);
                lsum += p;
                #pragma unroll
                for (int i = 0; i < 32; i++)
                    o[i] = fmaf(p, Vs[kk][c + 4*i], o[i]);
            }
        }
        __syncthreads();
    }

    float inv = 1.0f / lsum;
    float* op = g_att + ((size_t)(b*L + qpos) * NH + h) * HD;
    #pragma unroll
    for (int i = 0; i < 32; i++) op[c + 4*i] = o[i] * inv;
}

// ---------------- launch ------------------------------------------------------
extern "C" void kernel_launch(void* const* d_in, const int* in_sizes, int n_in,
                              void* d_out, int out_size) {
    const float* hs = (const float*)d_in[0];
    const float* Wq = (const float*)d_in[1];
    const float* Wk = (const float*)d_in[2];
    const float* Wv = (const float*)d_in[3];
    const float* Wo = (const float*)d_in[4];
    const float* qw = (const float*)d_in[5];
    const float* kw = (const float*)d_in[6];
    float* out = (float*)d_out;

    float *pq, *pk, *pv, *pa;
    cudaGetSymbolAddress((void**)&pq, g_q);
    cudaGetSymbolAddress((void**)&pk, g_k);
    cudaGetSymbolAddress((void**)&pv, g_v);
    cudaGetSymbolAddress((void**)&pa, g_att);

    rope_table_kernel<<<(L*(HD/2) + 255)/256, 256>>>();

    sgemm_kernel<<<dim3((NH*HD)/BN,  BL/BM), 256>>>(hs, Wq, pq, BL, NH*HD,  HS);
    sgemm_kernel<<<dim3((NKV*HD)/BN, BL/BM), 256>>>(hs, Wk, pk, BL, NKV*HD, HS);
    sgemm_kernel<<<dim3((NKV*HD)/BN, BL/BM), 256>>>(hs, Wv, pv, BL, NKV*HD, HS);

    norm_rope_kernel<<<BL*NH,  HD>>>(pq, qw, NH);
    norm_rope_kernel<<<BL*NKV, HD>>>(pk, kw, NKV);

    attn_kernel<<<dim3(L/QB, NH, B), 128>>>();

    sgemm_kernel<<<dim3(HS/BN, BL/BM), 256>>>(pa, Wo, out, BL, HS, NH*HD);
}

// round 15
// speedup vs baseline: 1.0095x; 1.0095x over previous
#include <cuda_runtime.h>
#include <math.h>

#define B   2
#define L   2048
#define HS  2048
#define NH  16
#define NKV 4
#define HD  128
#define BL  (B*L)
#define EPS 1e-6f
#define SCALE 0.08838834764831845f   // 128^-0.5

// ---------------- scratch (static device memory: alloc-guard safe) ----------
__device__ float g_q[(size_t)BL*NH*HD];     // 33.5 MB
__device__ float g_k[(size_t)BL*NKV*HD];    // 8.4 MB
__device__ float g_v[(size_t)BL*NKV*HD];    // 8.4 MB
__device__ float g_att[(size_t)BL*NH*HD];   // 33.5 MB
__device__ float g_cos[L*(HD/2)];
__device__ float g_sin[L*(HD/2)];

// ---------------- RoPE table (fp64 for accuracy, tiny kernel) ---------------
__global__ void rope_table_kernel() {
    int idx = blockIdx.x * blockDim.x + threadIdx.x;
    if (idx >= L*(HD/2)) return;
    int l = idx / (HD/2);
    int i = idx % (HD/2);
    // inv_freq = 10000^(-i/64) = exp(-i * ln(10000)/64)
    double inv = exp(-(double)i * (9.210340371976184 / 64.0));
    double a = (double)l * inv;
    g_cos[idx] = (float)cos(a);
    g_sin[idx] = (float)sin(a);
}

// ---------------- tiled fp32 SGEMM: C[M,N] = A[M,K] @ Bm[K,N] ----------------
#define BM 64
#define BN 64
#define BK 16
__global__ __launch_bounds__(256)
void sgemm_kernel(const float* __restrict__ A, const float* __restrict__ Bm,
                  float* __restrict__ C, int M, int N, int K) {
    __shared__ float As[BK][BM+1];
    __shared__ float Bs[BK][BN];
    int tid = threadIdx.x;
    int tx = tid & 15, ty = tid >> 4;
    int bm = blockIdx.y * BM, bn = blockIdx.x * BN;
    int arow = tid >> 2,  acol = (tid & 3) << 2;     // A: 64 rows x 16 cols, float4/thread
    int brow = tid >> 4,  bcol = (tid & 15) << 2;    // B: 16 rows x 64 cols, float4/thread
    const float* Aptr = A + (size_t)(bm + arow) * K + acol;
    const float* Bptr = Bm + (size_t)brow * N + bn + bcol;
    float acc[4][4] = {};
    for (int k0 = 0; k0 < K; k0 += BK) {
        float4 av = *(const float4*)(Aptr + k0);
        As[acol+0][arow] = av.x; As[acol+1][arow] = av.y;
        As[acol+2][arow] = av.z; As[acol+3][arow] = av.w;
        float4 bv = *(const float4*)(Bptr + (size_t)k0 * N);
        *(float4*)&Bs[brow][bcol] = bv;
        __syncthreads();
        #pragma unroll
        for (int k = 0; k < BK; k++) {
            float ra[4], rb[4];
            #pragma unroll
            for (int i = 0; i < 4; i++) ra[i] = As[k][(ty<<2)+i];
            #pragma unroll
            for (int j = 0; j < 4; j++) rb[j] = Bs[k][(tx<<2)+j];
            #pragma unroll
            for (int i = 0; i < 4; i++)
                #pragma unroll
                for (int j = 0; j < 4; j++)
                    acc[i][j] = fmaf(ra[i], rb[j], acc[i][j]);
        }
        __syncthreads();
    }
    #pragma unroll
    for (int i = 0; i < 4; i++) {
        float4 v = make_float4(acc[i][0], acc[i][1], acc[i][2], acc[i][3]);
        *(float4*)&C[(size_t)(bm + (ty<<2) + i) * N + bn + (tx<<2)] = v;
    }
}

// ---------------- fused RMSNorm (over HD) + RoPE, in-place -------------------
__global__ __launch_bounds__(HD)
void norm_rope_kernel(float* __restrict__ x, const float* __restrict__ w, int nheads) {
    int idx = blockIdx.x;              // (b*L + l)*nheads + h
    int tok = idx / nheads;
    int l   = tok % L;
    int d   = threadIdx.x;             // 0..127
    float* xp = x + (size_t)idx * HD;
    float v = xp[d];
    float ss = v * v;
    #pragma unroll
    for (int o = 16; o; o >>= 1) ss += __shfl_xor_sync(0xffffffffu, ss, o);
    __shared__ float wsum[4];
    if ((d & 31) == 0) wsum[d >> 5] = ss;
    __syncthreads();
    float total = wsum[0] + wsum[1] + wsum[2] + wsum[3];
    float r = rsqrtf(total * (1.0f/HD) + EPS);
    float xn = v * r * w[d];
    __shared__ float sx[HD];
    sx[d] = xn;
    __syncthreads();
    int fi = d & 63;
    float cz = g_cos[l*(HD/2) + fi];
    float sz = g_sin[l*(HD/2) + fi];
    float out;
    if (d < 64) out = xn * cz - sx[d+64] * sz;   // x1*cos - x2*sin
    else        out = xn * cz + sx[d-64] * sz;   // x2*cos + x1*sin
    xp[d] = out;
}

// ---------------- flash-style causal GQA attention ---------------------------
// 32 queries/block, 4 threads per query, each thread owns dims {c, c+4, ..., c+124}.
// Interleaved dim mapping -> smem reads hit 4 distinct banks (conflict-free).
#define QB 32
#define KT 32
__global__ __launch_bounds__(128)
void attn_kernel() {
    int b = blockIdx.z, h = blockIdx.y, qt = blockIdx.x;
    int j = h & (NKV - 1);             // GQA: q head h -> kv head h % NKV
    int tid = threadIdx.x;
    int ql = tid >> 2, c = tid & 3;
    int qpos = qt * QB + ql;

    const float* qptr = g_q + ((size_t)(b*L + qpos) * NH + h) * HD;
    float qr[32];
    #pragma unroll
    for (int i = 0; i < 32; i++) qr[i] = qptr[c + 4*i] * SCALE;

    float o[32];
    #pragma unroll
    for (int i = 0; i < 32; i++) o[i] = 0.f;
    float m = -INFINITY, lsum = 0.f;

    __shared__ float Ks[KT][HD];
    __shared__ float Vs[KT][HD];

    for (int kt = 0; kt <= qt; kt++) {
        // cooperative load: 32x128 floats each for K and V, 8 float4 per thread
        #pragma unroll
        for (int t = 0; t < 8; t++) {
            int fi  = tid + t * 128;
            int row = fi >> 5;
            int col = (fi & 31) << 2;
            size_t goff = ((size_t)(b*L + kt*KT + row) * NKV + j) * HD + col;
            *(float4*)&Ks[row][col] = *(const float4*)(g_k + goff);
            *(float4*)&Vs[row][col] = *(const float4*)(g_v + goff);
        }
        __syncthreads();

        #pragma unroll 4
        for (int kk = 0; kk < KT; kk++) {
            float s = 0.f;
            #pragma unroll
            for (int i = 0; i < 32; i++)
                s = fmaf(qr[i], Ks[kk][c + 4*i], s);
            s += __shfl_xor_sync(0xffffffffu, s, 1);
            s += __shfl_xor_sync(0xffffffffu, s, 2);
            if (kt*KT + kk <= qpos) {
                if (s > m) {                      // rescale only on new max
                    float corr = __expf(m - s);   // m=-inf first time -> corr=0
                    lsum *= corr;
                    #pragma unroll
                    for (int i = 0; i < 32; i++) o[i] *= corr;
                    m = s;
                }
                float p = __expf(s - m);
                lsum += p;
                #pragma unroll
                for (int i = 0; i < 32; i++)
                    o[i] = fmaf(p, Vs[kk][c + 4*i], o[i]);
            }
        }
        __syncthreads();
    }

    float inv = 1.0f / lsum;
    float* op = g_att + ((size_t)(b*L + qpos) * NH + h) * HD;
    #pragma unroll
    for (int i = 0; i < 32; i++) op[c + 4*i] = o[i] * inv;
}

// ---------------- launch ------------------------------------------------------
extern "C" void kernel_launch(void* const* d_in, const int* in_sizes, int n_in,
                              void* d_out, int out_size) {
    const float* hs = (const float*)d_in[0];
    const float* Wq = (const float*)d_in[1];
    const float* Wk = (const float*)d_in[2];
    const float* Wv = (const float*)d_in[3];
    const float* Wo = (const float*)d_in[4];
    const float* qw = (const float*)d_in[5];
    const float* kw = (const float*)d_in[6];
    float* out = (float*)d_out;

    float *pq, *pk, *pv, *pa;
    cudaGetSymbolAddress((void**)&pq, g_q);
    cudaGetSymbolAddress((void**)&pk, g_k);
    cudaGetSymbolAddress((void**)&pv, g_v);
    cudaGetSymbolAddress((void**)&pa, g_att);

    rope_table_kernel<<<(L*(HD/2) + 255)/256, 256>>>();

    sgemm_kernel<<<dim3((NH*HD)/BN,  BL/BM), 256>>>(hs, Wq, pq, BL, NH*HD,  HS);
    sgemm_kernel<<<dim3((NKV*HD)/BN, BL/BM), 256>>>(hs, Wk, pk, BL, NKV*HD, HS);
    sgemm_kernel<<<dim3((NKV*HD)/BN, BL/BM), 256>>>(hs, Wv, pv, BL, NKV*HD, HS);

    norm_rope_kernel<<<BL*NH,  HD>>>(pq, qw, NH);
    norm_rope_kernel<<<BL*NKV, HD>>>(pk, kw, NKV);

    attn_kernel<<<dim3(L/QB, NH, B), 128>>>();

    sgemm_kernel<<<dim3(HS/BN, BL/BM), 256>>>(pa, Wo, out, BL, HS, NH*HD);
}